// round 1
// baseline (speedup 1.0000x reference)
#include <cuda_runtime.h>

// ---------------------------------------------------------------------------
// DeepFM collapsed:
//   Y[b, 0:256]   = mv@(Wm[:, :256]@W1[:256]) + uv@(Wu[:, :256]@W1[256:]) + c   -> relu -> h1
//   Y[b, 256:272] = ms  (column-group sums of movie tower, linear)
//   Y[b, 272:288] = us
//   Y[b, 288]     = fm_additive
//   out = relu(h1@W2+b2)@W3 + b3 + dot(ms,us) + additive
// ---------------------------------------------------------------------------

#define BATCH 16384
#define KDIM  1024
#define NOUT  289
#define NPAD  320
#define H1DIM 256
#define H2DIM 128

// Scratch (zero-initialized at module load; pad columns of g_Wbig stay 0 forever).
__device__ float g_Wbig[KDIM * NPAD];
__device__ float g_cbias[NPAD];
__device__ float g_H1[BATCH * H1DIM];
__device__ float g_MS[BATCH * 16];
__device__ float g_US[BATCH * 16];
__device__ float g_ADD[BATCH];

// ---------------------------------------------------------------------------
// K0a: C(64x64 tiles) = A[M,K] @ B[K,N] into g_Wbig (offset), fp32 tiled.
// Used for Wm[:, :256] @ W1[:256,:] and Wu[:, :256] @ W1[256:,:].
// M=512, N=256, K=256 per call. BM=BN=64, BK=16, 256 thr, TM=TN=4.
// ---------------------------------------------------------------------------
__global__ __launch_bounds__(256) void k_combine_gemm(
    const float* __restrict__ A, int lda,
    const float* __restrict__ Bw, int ldb,
    int c_offset, int K)
{
    __shared__ float As[16][64];
    __shared__ float Bs[16][64];
    int t  = threadIdx.x;
    int tx = t & 15, ty = t >> 4;
    int m0 = blockIdx.y * 64, n0 = blockIdx.x * 64;
    float acc[4][4] = {};

    for (int k0 = 0; k0 < K; k0 += 16) {
        {   // A tile 64x16 (lda=257 is odd -> scalar loads), stored transposed
            int row = t >> 2;
            int kq  = (t & 3) << 2;
            const float* ap = A + (m0 + row) * lda + k0 + kq;
            #pragma unroll
            for (int i = 0; i < 4; i++) As[kq + i][row] = ap[i];
        }
        {   // B tile 16x64, float4
            int kr = t >> 4;
            int nq = (t & 15) << 2;
            float4 v = *reinterpret_cast<const float4*>(Bw + (k0 + kr) * ldb + n0 + nq);
            *reinterpret_cast<float4*>(&Bs[kr][nq]) = v;
        }
        __syncthreads();
        #pragma unroll
        for (int kk = 0; kk < 16; kk++) {
            float a[4], b[4];
            #pragma unroll
            for (int i = 0; i < 4; i++) a[i] = As[kk][ty * 4 + i];
            #pragma unroll
            for (int j = 0; j < 4; j++) b[j] = Bs[kk][tx * 4 + j];
            #pragma unroll
            for (int i = 0; i < 4; i++)
                #pragma unroll
                for (int j = 0; j < 4; j++) acc[i][j] += a[i] * b[j];
        }
        __syncthreads();
    }
    #pragma unroll
    for (int i = 0; i < 4; i++)
        #pragma unroll
        for (int j = 0; j < 4; j++)
            g_Wbig[c_offset + (m0 + ty * 4 + i) * NPAD + n0 + tx * 4 + j] = acc[i][j];
}

// ---------------------------------------------------------------------------
// K0b: ms/us/additive weight columns + combined bias vector.
// ---------------------------------------------------------------------------
__global__ void k_small(const float* __restrict__ Wm, const float* __restrict__ bm,
                        const float* __restrict__ Wu, const float* __restrict__ bu,
                        const float* __restrict__ W1, const float* __restrict__ b1)
{
    int t = blockIdx.x * blockDim.x + threadIdx.x;
    if (t < KDIM * 16) {
        int k = t >> 4, d = t & 15;
        float s = 0.f;
        if (k < 512) {
            #pragma unroll
            for (int i = 0; i < 16; i++) s += Wm[k * 257 + i * 16 + d];
            g_Wbig[k * NPAD + 256 + d] = s;
            if (d == 0) g_Wbig[k * NPAD + 288] = Wm[k * 257 + 256];
        } else {
            int ku = k - 512;
            #pragma unroll
            for (int i = 0; i < 16; i++) s += Wu[ku * 257 + i * 16 + d];
            g_Wbig[k * NPAD + 272 + d] = s;
            if (d == 0) g_Wbig[k * NPAD + 288] = Wu[ku * 257 + 256];
        }
        return;
    }
    int c = t - KDIM * 16;
    if (c >= 0 && c < NOUT) {
        float v;
        if (c < 256) {
            v = b1[c];
            for (int j = 0; j < 256; j++) v += bm[j] * W1[j * 256 + c];
            for (int j = 0; j < 256; j++) v += bu[j] * W1[(256 + j) * 256 + c];
        } else if (c < 272) {
            int d = c - 256; v = 0.f;
            #pragma unroll
            for (int i = 0; i < 16; i++) v += bm[i * 16 + d];
        } else if (c < 288) {
            int d = c - 272; v = 0.f;
            #pragma unroll
            for (int i = 0; i < 16; i++) v += bu[i * 16 + d];
        } else {
            v = bm[256] + bu[256];
        }
        g_cbias[c] = v;
    }
}

// ---------------------------------------------------------------------------
// K1: main GEMM [16384,1024] @ [1024, 289(pad 320)] with split epilogue.
// BM=128, BN=64, BK=16, 256 threads, TM=8, TN=4.
// ---------------------------------------------------------------------------
__global__ __launch_bounds__(256) void k_main_gemm(
    const float* __restrict__ mv, const float* __restrict__ uv)
{
    __shared__ float As[16][128];
    __shared__ float Bs[16][64];
    int t  = threadIdx.x;
    int tx = t & 15, ty = t >> 4;
    int m0 = blockIdx.y * 128;
    int n0 = blockIdx.x * 64;
    float acc[8][4] = {};

    for (int k0 = 0; k0 < KDIM; k0 += 16) {
        #pragma unroll
        for (int l = 0; l < 2; l++) {           // A tile 128x16 via float4
            int f   = t + l * 256;
            int row = f >> 2;
            int kq  = (f & 3) << 2;
            int kg  = k0 + kq;
            const float* src = (kg < 512) ? (mv + (m0 + row) * 512 + kg)
                                          : (uv + (m0 + row) * 512 + kg - 512);
            float4 v = *reinterpret_cast<const float4*>(src);
            As[kq + 0][row] = v.x; As[kq + 1][row] = v.y;
            As[kq + 2][row] = v.z; As[kq + 3][row] = v.w;
        }
        {   // B tile 16x64
            int kr = t >> 4;
            int nq = (t & 15) << 2;
            float4 v = *reinterpret_cast<const float4*>(g_Wbig + (k0 + kr) * NPAD + n0 + nq);
            *reinterpret_cast<float4*>(&Bs[kr][nq]) = v;
        }
        __syncthreads();
        #pragma unroll
        for (int kk = 0; kk < 16; kk++) {
            float a[8], b[4];
            #pragma unroll
            for (int i = 0; i < 8; i++) a[i] = As[kk][ty * 8 + i];
            #pragma unroll
            for (int j = 0; j < 4; j++) b[j] = Bs[kk][tx * 4 + j];
            #pragma unroll
            for (int i = 0; i < 8; i++)
                #pragma unroll
                for (int j = 0; j < 4; j++) acc[i][j] += a[i] * b[j];
        }
        __syncthreads();
    }

    #pragma unroll
    for (int i = 0; i < 8; i++) {
        int m = m0 + ty * 8 + i;
        #pragma unroll
        for (int j = 0; j < 4; j++) {
            int n = n0 + tx * 4 + j;
            if (n >= NOUT) continue;
            float v = acc[i][j] + g_cbias[n];
            if (n < 256)       g_H1[m * H1DIM + n]      = fmaxf(v, 0.f);
            else if (n < 272)  g_MS[m * 16 + (n - 256)] = v;
            else if (n < 288)  g_US[m * 16 + (n - 272)] = v;
            else               g_ADD[m]                 = v;
        }
    }
}

// ---------------------------------------------------------------------------
// K2: fused tail. h2 = relu(h1@W2 + b2); out = h2@W3 + b3 + dot(ms,us) + add.
// Block: 64 rows; 256 threads = 8 col-groups x 32 row-groups(2 rows each).
// ---------------------------------------------------------------------------
__global__ __launch_bounds__(256) void k_mlp_tail(
    const float* __restrict__ W2, const float* __restrict__ b2,
    const float* __restrict__ W3, const float* __restrict__ b3,
    float* __restrict__ out)
{
    __shared__ float Hs[64][33];      // padded to dodge bank conflicts
    __shared__ float W2s[32][128];
    __shared__ float b2s[128];
    __shared__ float w3s[128];
    __shared__ float ps[64][9];

    int t    = threadIdx.x;
    int tcol = t & 7;                 // 8 groups of 16 cols
    int trg  = t >> 3;                // 32 groups of 2 rows
    int m0   = blockIdx.x * 64;

    if (t < 128) { b2s[t] = b2[t]; w3s[t] = W3[t]; }
    __syncthreads();

    float acc[2][16];
    #pragma unroll
    for (int c = 0; c < 16; c++) { acc[0][c] = b2s[tcol * 16 + c]; acc[1][c] = acc[0][c]; }

    for (int kc = 0; kc < H1DIM; kc += 32) {
        {   // Hs: 64x32 floats, 2 float4 gl loads per thread
            #pragma unroll
            for (int l = 0; l < 2; l++) {
                int f   = t + l * 256;
                int row = f >> 3;
                int q   = (f & 7) << 2;
                float4 v = *reinterpret_cast<const float4*>(g_H1 + (m0 + row) * H1DIM + kc + q);
                Hs[row][q + 0] = v.x; Hs[row][q + 1] = v.y;
                Hs[row][q + 2] = v.z; Hs[row][q + 3] = v.w;
            }
            // W2s: 32x128 floats, 4 float4 per thread
            #pragma unroll
            for (int l = 0; l < 4; l++) {
                int f = t + l * 256;
                int k = f >> 5;
                int q = (f & 31) << 2;
                float4 v = *reinterpret_cast<const float4*>(W2 + (kc + k) * H2DIM + q);
                *reinterpret_cast<float4*>(&W2s[k][q]) = v;
            }
        }
        __syncthreads();
        #pragma unroll
        for (int kk = 0; kk < 32; kk++) {
            float h0 = Hs[trg * 2 + 0][kk];
            float h1 = Hs[trg * 2 + 1][kk];
            #pragma unroll
            for (int c4 = 0; c4 < 4; c4++) {
                float4 w = *reinterpret_cast<const float4*>(&W2s[kk][tcol * 16 + c4 * 4]);
                acc[0][c4 * 4 + 0] += h0 * w.x; acc[1][c4 * 4 + 0] += h1 * w.x;
                acc[0][c4 * 4 + 1] += h0 * w.y; acc[1][c4 * 4 + 1] += h1 * w.y;
                acc[0][c4 * 4 + 2] += h0 * w.z; acc[1][c4 * 4 + 2] += h1 * w.z;
                acc[0][c4 * 4 + 3] += h0 * w.w; acc[1][c4 * 4 + 3] += h1 * w.w;
            }
        }
        __syncthreads();
    }

    // relu + partial dot with W3
    float p0 = 0.f, p1 = 0.f;
    #pragma unroll
    for (int c = 0; c < 16; c++) {
        float w3v = w3s[tcol * 16 + c];
        p0 += fmaxf(acc[0][c], 0.f) * w3v;
        p1 += fmaxf(acc[1][c], 0.f) * w3v;
    }
    ps[trg * 2 + 0][tcol] = p0;
    ps[trg * 2 + 1][tcol] = p1;
    __syncthreads();

    if (t < 64) {
        int   m = m0 + t;
        float s = b3[0] + g_ADD[m];
        #pragma unroll
        for (int j = 0; j < 8; j++) s += ps[t][j];
        #pragma unroll
        for (int i = 0; i < 16; i++) s += g_MS[m * 16 + i] * g_US[m * 16 + i];
        out[m] = s;
    }
}

// ---------------------------------------------------------------------------
extern "C" void kernel_launch(void* const* d_in, const int* in_sizes, int n_in,
                              void* d_out, int out_size)
{
    const float* mv = (const float*)d_in[0];
    const float* uv = (const float*)d_in[1];
    const float* Wm = (const float*)d_in[2];
    const float* bm = (const float*)d_in[3];
    const float* Wu = (const float*)d_in[4];
    const float* bu = (const float*)d_in[5];
    const float* W1 = (const float*)d_in[6];
    const float* b1 = (const float*)d_in[7];
    const float* W2 = (const float*)d_in[8];
    const float* b2 = (const float*)d_in[9];
    const float* W3 = (const float*)d_in[10];
    const float* b3 = (const float*)d_in[11];
    float* out = (float*)d_out;

    // Weight precompute (fresh every call — no caching).
    k_combine_gemm<<<dim3(4, 8), 256>>>(Wm, 257, W1,              256, 0,           256);
    k_combine_gemm<<<dim3(4, 8), 256>>>(Wu, 257, W1 + 256 * 256,  256, 512 * NPAD,  256);
    k_small<<<(KDIM * 16 + NOUT + 255) / 256, 256>>>(Wm, bm, Wu, bu, W1, b1);

    // Main GEMM + split epilogue.
    k_main_gemm<<<dim3(5, BATCH / 128), 256>>>(mv, uv);

    // Fused MLP tail + FM terms.
    k_mlp_tail<<<BATCH / 64, 256>>>(W2, b2, W3, b3, out);
}

// round 2
// speedup vs baseline: 1.0028x; 1.0028x over previous
#include <cuda_runtime.h>

// ---------------------------------------------------------------------------
// DeepFM collapsed:
//   Y[b, 0:256]   = mv@(Wm[:, :256]@W1[:256]) + uv@(Wu[:, :256]@W1[256:]) + c   -> relu -> h1
//   Y[b, 256:272] = ms  (column-group sums of movie tower, linear)
//   Y[b, 272:288] = us
//   Y[b, 288]     = fm_additive
//   out = relu(h1@W2+b2)@W3 + b3 + dot(ms,us) + additive
// ---------------------------------------------------------------------------

#define BATCH 16384
#define KDIM  1024
#define NOUT  289
#define NPAD  320
#define H1DIM 256
#define H2DIM 128

// Scratch (zero-initialized at module load; pad columns of g_Wbig stay 0 forever).
__device__ float g_Wbig[KDIM * NPAD];
__device__ float g_cbias[NPAD];
__device__ float g_H1[BATCH * H1DIM];
__device__ float g_MS[BATCH * 16];
__device__ float g_US[BATCH * 16];
__device__ float g_ADD[BATCH];

// ---------------------------------------------------------------------------
// K0a: C(64x64 tiles) = A[M,K] @ B[K,N] into g_Wbig (offset), fp32 tiled.
// Used for Wm[:, :256] @ W1[:256,:] and Wu[:, :256] @ W1[256:,:].
// M=512, N=256, K=256 per call. BM=BN=64, BK=16, 256 thr, TM=TN=4.
// ---------------------------------------------------------------------------
__global__ __launch_bounds__(256) void k_combine_gemm(
    const float* __restrict__ A, int lda,
    const float* __restrict__ Bw, int ldb,
    int c_offset, int K)
{
    __shared__ float As[16][64];
    __shared__ float Bs[16][64];
    int t  = threadIdx.x;
    int tx = t & 15, ty = t >> 4;
    int m0 = blockIdx.y * 64, n0 = blockIdx.x * 64;
    float acc[4][4] = {};

    for (int k0 = 0; k0 < K; k0 += 16) {
        {   // A tile 64x16 (lda=257 is odd -> scalar loads), stored transposed
            int row = t >> 2;
            int kq  = (t & 3) << 2;
            const float* ap = A + (m0 + row) * lda + k0 + kq;
            #pragma unroll
            for (int i = 0; i < 4; i++) As[kq + i][row] = ap[i];
        }
        {   // B tile 16x64, float4
            int kr = t >> 4;
            int nq = (t & 15) << 2;
            float4 v = *reinterpret_cast<const float4*>(Bw + (k0 + kr) * ldb + n0 + nq);
            *reinterpret_cast<float4*>(&Bs[kr][nq]) = v;
        }
        __syncthreads();
        #pragma unroll
        for (int kk = 0; kk < 16; kk++) {
            float a[4], b[4];
            #pragma unroll
            for (int i = 0; i < 4; i++) a[i] = As[kk][ty * 4 + i];
            #pragma unroll
            for (int j = 0; j < 4; j++) b[j] = Bs[kk][tx * 4 + j];
            #pragma unroll
            for (int i = 0; i < 4; i++)
                #pragma unroll
                for (int j = 0; j < 4; j++) acc[i][j] += a[i] * b[j];
        }
        __syncthreads();
    }
    #pragma unroll
    for (int i = 0; i < 4; i++)
        #pragma unroll
        for (int j = 0; j < 4; j++)
            g_Wbig[c_offset + (m0 + ty * 4 + i) * NPAD + n0 + tx * 4 + j] = acc[i][j];
}

// ---------------------------------------------------------------------------
// K0b: ms/us/additive weight columns + combined bias vector.
// ---------------------------------------------------------------------------
__global__ void k_small(const float* __restrict__ Wm, const float* __restrict__ bm,
                        const float* __restrict__ Wu, const float* __restrict__ bu,
                        const float* __restrict__ W1, const float* __restrict__ b1)
{
    int t = blockIdx.x * blockDim.x + threadIdx.x;
    if (t < KDIM * 16) {
        int k = t >> 4, d = t & 15;
        float s = 0.f;
        if (k < 512) {
            #pragma unroll
            for (int i = 0; i < 16; i++) s += Wm[k * 257 + i * 16 + d];
            g_Wbig[k * NPAD + 256 + d] = s;
            if (d == 0) g_Wbig[k * NPAD + 288] = Wm[k * 257 + 256];
        } else {
            int ku = k - 512;
            #pragma unroll
            for (int i = 0; i < 16; i++) s += Wu[ku * 257 + i * 16 + d];
            g_Wbig[k * NPAD + 272 + d] = s;
            if (d == 0) g_Wbig[k * NPAD + 288] = Wu[ku * 257 + 256];
        }
        return;
    }
    int c = t - KDIM * 16;
    if (c >= 0 && c < NOUT) {
        float v;
        if (c < 256) {
            v = b1[c];
            for (int j = 0; j < 256; j++) v += bm[j] * W1[j * 256 + c];
            for (int j = 0; j < 256; j++) v += bu[j] * W1[(256 + j) * 256 + c];
        } else if (c < 272) {
            int d = c - 256; v = 0.f;
            #pragma unroll
            for (int i = 0; i < 16; i++) v += bm[i * 16 + d];
        } else if (c < 288) {
            int d = c - 272; v = 0.f;
            #pragma unroll
            for (int i = 0; i < 16; i++) v += bu[i * 16 + d];
        } else {
            v = bm[256] + bu[256];
        }
        g_cbias[c] = v;
    }
}

// ---------------------------------------------------------------------------
// K1: main GEMM [16384,1024] @ [1024, 289(pad 320)] with split epilogue.
// BM=128, BN=64, BK=16, 256 threads, TM=8, TN=4.
// ---------------------------------------------------------------------------
__global__ __launch_bounds__(256) void k_main_gemm(
    const float* __restrict__ mv, const float* __restrict__ uv)
{
    __shared__ float As[16][128];
    __shared__ float Bs[16][64];
    int t  = threadIdx.x;
    int tx = t & 15, ty = t >> 4;
    int m0 = blockIdx.y * 128;
    int n0 = blockIdx.x * 64;
    float acc[8][4] = {};

    for (int k0 = 0; k0 < KDIM; k0 += 16) {
        #pragma unroll
        for (int l = 0; l < 2; l++) {           // A tile 128x16 via float4
            int f   = t + l * 256;
            int row = f >> 2;
            int kq  = (f & 3) << 2;
            int kg  = k0 + kq;
            const float* src = (kg < 512) ? (mv + (m0 + row) * 512 + kg)
                                          : (uv + (m0 + row) * 512 + kg - 512);
            float4 v = *reinterpret_cast<const float4*>(src);
            As[kq + 0][row] = v.x; As[kq + 1][row] = v.y;
            As[kq + 2][row] = v.z; As[kq + 3][row] = v.w;
        }
        {   // B tile 16x64
            int kr = t >> 4;
            int nq = (t & 15) << 2;
            float4 v = *reinterpret_cast<const float4*>(g_Wbig + (k0 + kr) * NPAD + n0 + nq);
            *reinterpret_cast<float4*>(&Bs[kr][nq]) = v;
        }
        __syncthreads();
        #pragma unroll
        for (int kk = 0; kk < 16; kk++) {
            float a[8], b[4];
            #pragma unroll
            for (int i = 0; i < 8; i++) a[i] = As[kk][ty * 8 + i];
            #pragma unroll
            for (int j = 0; j < 4; j++) b[j] = Bs[kk][tx * 4 + j];
            #pragma unroll
            for (int i = 0; i < 8; i++)
                #pragma unroll
                for (int j = 0; j < 4; j++) acc[i][j] += a[i] * b[j];
        }
        __syncthreads();
    }

    #pragma unroll
    for (int i = 0; i < 8; i++) {
        int m = m0 + ty * 8 + i;
        #pragma unroll
        for (int j = 0; j < 4; j++) {
            int n = n0 + tx * 4 + j;
            if (n >= NOUT) continue;
            float v = acc[i][j] + g_cbias[n];
            if (n < 256)       g_H1[m * H1DIM + n]      = fmaxf(v, 0.f);
            else if (n < 272)  g_MS[m * 16 + (n - 256)] = v;
            else if (n < 288)  g_US[m * 16 + (n - 272)] = v;
            else               g_ADD[m]                 = v;
        }
    }
}

// ---------------------------------------------------------------------------
// K2: fused tail. h2 = relu(h1@W2 + b2); out = h2@W3 + b3 + dot(ms,us) + add.
// Block: 64 rows; 256 threads = 8 col-groups x 32 row-groups(2 rows each).
// ---------------------------------------------------------------------------
__global__ __launch_bounds__(256) void k_mlp_tail(
    const float* __restrict__ W2, const float* __restrict__ b2,
    const float* __restrict__ W3, const float* __restrict__ b3,
    float* __restrict__ out)
{
    __shared__ float Hs[64][33];      // padded to dodge bank conflicts
    __shared__ float W2s[32][128];
    __shared__ float b2s[128];
    __shared__ float w3s[128];
    __shared__ float ps[64][9];

    int t    = threadIdx.x;
    int tcol = t & 7;                 // 8 groups of 16 cols
    int trg  = t >> 3;                // 32 groups of 2 rows
    int m0   = blockIdx.x * 64;

    if (t < 128) { b2s[t] = b2[t]; w3s[t] = W3[t]; }
    __syncthreads();

    float acc[2][16];
    #pragma unroll
    for (int c = 0; c < 16; c++) { acc[0][c] = b2s[tcol * 16 + c]; acc[1][c] = acc[0][c]; }

    for (int kc = 0; kc < H1DIM; kc += 32) {
        {   // Hs: 64x32 floats, 2 float4 gl loads per thread
            #pragma unroll
            for (int l = 0; l < 2; l++) {
                int f   = t + l * 256;
                int row = f >> 3;
                int q   = (f & 7) << 2;
                float4 v = *reinterpret_cast<const float4*>(g_H1 + (m0 + row) * H1DIM + kc + q);
                Hs[row][q + 0] = v.x; Hs[row][q + 1] = v.y;
                Hs[row][q + 2] = v.z; Hs[row][q + 3] = v.w;
            }
            // W2s: 32x128 floats, 4 float4 per thread
            #pragma unroll
            for (int l = 0; l < 4; l++) {
                int f = t + l * 256;
                int k = f >> 5;
                int q = (f & 31) << 2;
                float4 v = *reinterpret_cast<const float4*>(W2 + (kc + k) * H2DIM + q);
                *reinterpret_cast<float4*>(&W2s[k][q]) = v;
            }
        }
        __syncthreads();
        #pragma unroll
        for (int kk = 0; kk < 32; kk++) {
            float h0 = Hs[trg * 2 + 0][kk];
            float h1 = Hs[trg * 2 + 1][kk];
            #pragma unroll
            for (int c4 = 0; c4 < 4; c4++) {
                float4 w = *reinterpret_cast<const float4*>(&W2s[kk][tcol * 16 + c4 * 4]);
                acc[0][c4 * 4 + 0] += h0 * w.x; acc[1][c4 * 4 + 0] += h1 * w.x;
                acc[0][c4 * 4 + 1] += h0 * w.y; acc[1][c4 * 4 + 1] += h1 * w.y;
                acc[0][c4 * 4 + 2] += h0 * w.z; acc[1][c4 * 4 + 2] += h1 * w.z;
                acc[0][c4 * 4 + 3] += h0 * w.w; acc[1][c4 * 4 + 3] += h1 * w.w;
            }
        }
        __syncthreads();
    }

    // relu + partial dot with W3
    float p0 = 0.f, p1 = 0.f;
    #pragma unroll
    for (int c = 0; c < 16; c++) {
        float w3v = w3s[tcol * 16 + c];
        p0 += fmaxf(acc[0][c], 0.f) * w3v;
        p1 += fmaxf(acc[1][c], 0.f) * w3v;
    }
    ps[trg * 2 + 0][tcol] = p0;
    ps[trg * 2 + 1][tcol] = p1;
    __syncthreads();

    if (t < 64) {
        int   m = m0 + t;
        float s = b3[0] + g_ADD[m];
        #pragma unroll
        for (int j = 0; j < 8; j++) s += ps[t][j];
        #pragma unroll
        for (int i = 0; i < 16; i++) s += g_MS[m * 16 + i] * g_US[m * 16 + i];
        out[m] = s;
    }
}

// ---------------------------------------------------------------------------
extern "C" void kernel_launch(void* const* d_in, const int* in_sizes, int n_in,
                              void* d_out, int out_size)
{
    const float* mv = (const float*)d_in[0];
    const float* uv = (const float*)d_in[1];
    const float* Wm = (const float*)d_in[2];
    const float* bm = (const float*)d_in[3];
    const float* Wu = (const float*)d_in[4];
    const float* bu = (const float*)d_in[5];
    const float* W1 = (const float*)d_in[6];
    const float* b1 = (const float*)d_in[7];
    const float* W2 = (const float*)d_in[8];
    const float* b2 = (const float*)d_in[9];
    const float* W3 = (const float*)d_in[10];
    const float* b3 = (const float*)d_in[11];
    float* out = (float*)d_out;

    // Weight precompute (fresh every call — no caching).
    k_combine_gemm<<<dim3(4, 8), 256>>>(Wm, 257, W1,              256, 0,           256);
    k_combine_gemm<<<dim3(4, 8), 256>>>(Wu, 257, W1 + 256 * 256,  256, 512 * NPAD,  256);
    k_small<<<(KDIM * 16 + NOUT + 255) / 256, 256>>>(Wm, bm, Wu, bu, W1, b1);

    // Main GEMM + split epilogue.
    k_main_gemm<<<dim3(5, BATCH / 128), 256>>>(mv, uv);

    // Fused MLP tail + FM terms.
    k_mlp_tail<<<BATCH / 64, 256>>>(W2, b2, W3, b3, out);
}

// round 5
// speedup vs baseline: 2.4204x; 2.4137x over previous
#include <cuda_runtime.h>
#include <cuda_bf16.h>
#include <cstdint>

#define BATCH 16384
#define KD    1024
#define NOUT  289
#define NPAD  320
#define H1D   256
#define H2D   128

// ---------------------------------------------------------------------------
// Device scratch (zero-initialized at load; g_Wbig pad columns stay 0 forever).
// ---------------------------------------------------------------------------
__device__ float         g_Wbig[KD * NPAD];
__device__ float         g_cbias[NPAD];
__device__ __nv_bfloat16 g_Ahi[BATCH * KD];
__device__ __nv_bfloat16 g_Alo[BATCH * KD];
__device__ __nv_bfloat16 g_Bthi[NPAD * KD];
__device__ __nv_bfloat16 g_Btlo[NPAD * KD];
__device__ __nv_bfloat16 g_Hhi[BATCH * H1D];
__device__ __nv_bfloat16 g_Hlo[BATCH * H1D];
__device__ __nv_bfloat16 g_W2thi[H2D * H1D];
__device__ __nv_bfloat16 g_W2tlo[H2D * H1D];
__device__ float         g_MS[BATCH * 16];
__device__ float         g_US[BATCH * 16];
__device__ float         g_ADD[BATCH];

// ---------------------------------------------------------------------------
// Helpers (base sm_103 PTX only: mma.sync / ldmatrix / cp.async)
// ---------------------------------------------------------------------------
static __device__ __forceinline__ uint32_t smem_u32(const void* p) {
    uint32_t a;
    asm("{ .reg .u64 t; cvta.to.shared.u64 t, %1; cvt.u32.u64 %0, t; }" : "=r"(a) : "l"(p));
    return a;
}
static __device__ __forceinline__ void cp16(uint32_t dst, const void* src) {
    asm volatile("cp.async.cg.shared.global [%0], [%1], 16;\n" :: "r"(dst), "l"(src));
}
#define CP_COMMIT() asm volatile("cp.async.commit_group;\n" ::: "memory")
#define CP_WAIT2()  asm volatile("cp.async.wait_group 2;\n" ::: "memory")

#define LDSM4(r0, r1, r2, r3, addr) \
    asm volatile("ldmatrix.sync.aligned.m8n8.x4.shared.b16 {%0,%1,%2,%3}, [%4];" \
                 : "=r"(r0), "=r"(r1), "=r"(r2), "=r"(r3) : "r"(addr))

#define MMA16816(c, a, b) \
    asm volatile("mma.sync.aligned.m16n8k16.row.col.f32.bf16.bf16.f32 " \
                 "{%0,%1,%2,%3},{%4,%5,%6,%7},{%8,%9},{%0,%1,%2,%3};" \
                 : "+f"((c)[0]), "+f"((c)[1]), "+f"((c)[2]), "+f"((c)[3]) \
                 : "r"((a)[0]), "r"((a)[1]), "r"((a)[2]), "r"((a)[3]), \
                   "r"((b)[0]), "r"((b)[1]))

#define SWZ(x) ((x) ^ (((x) >> 3) & 0x70))

static __device__ __forceinline__ void split2(float v, __nv_bfloat16& h, __nv_bfloat16& l) {
    h = __float2bfloat16(v);
    l = __float2bfloat16(v - __bfloat162float(h));
}
static __device__ __forceinline__ uint32_t pack_bf2(__nv_bfloat16 a, __nv_bfloat16 b) {
    __nv_bfloat162 p; p.x = a; p.y = b;
    return *reinterpret_cast<uint32_t*>(&p);
}

// ---------------------------------------------------------------------------
// K0a: Wbig[:, :256] = Wm[:, :256] @ W1[:256] (and Wu part), fp32 tiled.
// ---------------------------------------------------------------------------
__global__ __launch_bounds__(256) void k_combine_gemm(
    const float* __restrict__ A, int lda,
    const float* __restrict__ Bw, int ldb,
    int c_offset, int K)
{
    __shared__ float As[16][64];
    __shared__ float Bs[16][64];
    int t = threadIdx.x;
    int tx = t & 15, ty = t >> 4;
    int m0 = blockIdx.y * 64, n0 = blockIdx.x * 64;
    float acc[4][4] = {};

    for (int k0 = 0; k0 < K; k0 += 16) {
        {
            int row = t >> 2;
            int kq = (t & 3) << 2;
            const float* ap = A + (m0 + row) * lda + k0 + kq;
            #pragma unroll
            for (int i = 0; i < 4; i++) As[kq + i][row] = ap[i];
        }
        {
            int kr = t >> 4;
            int nq = (t & 15) << 2;
            float4 v = *reinterpret_cast<const float4*>(Bw + (k0 + kr) * ldb + n0 + nq);
            *reinterpret_cast<float4*>(&Bs[kr][nq]) = v;
        }
        __syncthreads();
        #pragma unroll
        for (int kk = 0; kk < 16; kk++) {
            float a[4], b[4];
            #pragma unroll
            for (int i = 0; i < 4; i++) a[i] = As[kk][ty * 4 + i];
            #pragma unroll
            for (int j = 0; j < 4; j++) b[j] = Bs[kk][tx * 4 + j];
            #pragma unroll
            for (int i = 0; i < 4; i++)
                #pragma unroll
                for (int j = 0; j < 4; j++) acc[i][j] += a[i] * b[j];
        }
        __syncthreads();
    }
    #pragma unroll
    for (int i = 0; i < 4; i++)
        #pragma unroll
        for (int j = 0; j < 4; j++)
            g_Wbig[c_offset + (m0 + ty * 4 + i) * NPAD + n0 + tx * 4 + j] = acc[i][j];
}

// ---------------------------------------------------------------------------
// K0b: ms/us/additive weight columns of Wbig + combined bias vector.
// ---------------------------------------------------------------------------
__global__ void k_small(const float* __restrict__ Wm, const float* __restrict__ bm,
                        const float* __restrict__ Wu, const float* __restrict__ bu,
                        const float* __restrict__ W1, const float* __restrict__ b1)
{
    int t = blockIdx.x * blockDim.x + threadIdx.x;
    if (t < KD * 16) {
        int k = t >> 4, d = t & 15;
        float s = 0.f;
        if (k < 512) {
            #pragma unroll
            for (int i = 0; i < 16; i++) s += Wm[k * 257 + i * 16 + d];
            g_Wbig[k * NPAD + 256 + d] = s;
            if (d == 0) g_Wbig[k * NPAD + 288] = Wm[k * 257 + 256];
        } else {
            int ku = k - 512;
            #pragma unroll
            for (int i = 0; i < 16; i++) s += Wu[ku * 257 + i * 16 + d];
            g_Wbig[k * NPAD + 272 + d] = s;
            if (d == 0) g_Wbig[k * NPAD + 288] = Wu[ku * 257 + 256];
        }
        return;
    }
    int c = t - KD * 16;
    if (c >= 0 && c < NOUT) {
        float v;
        if (c < 256) {
            v = b1[c];
            for (int j = 0; j < 256; j++) v += bm[j] * W1[j * 256 + c];
            for (int j = 0; j < 256; j++) v += bu[j] * W1[(256 + j) * 256 + c];
        } else if (c < 272) {
            int d = c - 256; v = 0.f;
            #pragma unroll
            for (int i = 0; i < 16; i++) v += bm[i * 16 + d];
        } else if (c < 288) {
            int d = c - 272; v = 0.f;
            #pragma unroll
            for (int i = 0; i < 16; i++) v += bu[i * 16 + d];
        } else {
            v = bm[256] + bu[256];
        }
        g_cbias[c] = v;
    }
}

// ---------------------------------------------------------------------------
// K0c: transpose+split Wbig -> Bt(hi/lo) [NPAD rows, KD k-major]; also W2 -> W2t.
// ---------------------------------------------------------------------------
__global__ void k_convB(const float* __restrict__ W2)
{
    int i = blockIdx.x * blockDim.x + threadIdx.x;
    if (i < NPAD * KD) {
        int n = i >> 10, k = i & 1023;
        __nv_bfloat16 h, l;
        split2(g_Wbig[k * NPAD + n], h, l);
        g_Bthi[i] = h; g_Btlo[i] = l;
        return;
    }
    int j = i - NPAD * KD;
    if (j < H2D * H1D) {
        int r = j >> 8, c = j & 255;          // W2t[r][c] = W2[c][r]
        __nv_bfloat16 h, l;
        split2(W2[c * H2D + r], h, l);
        g_W2thi[j] = h; g_W2tlo[j] = l;
    }
}

// ---------------------------------------------------------------------------
// K0d: split inputs -> Ahi/Alo bf16 [BATCH, 1024] (mv cols 0..511, uv 512..1023)
// ---------------------------------------------------------------------------
__global__ __launch_bounds__(256) void k_convA(const float* __restrict__ mv,
                                               const float* __restrict__ uv)
{
    int i = blockIdx.x * blockDim.x + threadIdx.x;   // one per 4 elems
    int base = i * 4;
    int row = base >> 10, k = base & 1023;
    const float* src = (k < 512) ? (mv + (size_t)row * 512 + k)
                                 : (uv + (size_t)row * 512 + k - 512);
    float4 v = *reinterpret_cast<const float4*>(src);
    __nv_bfloat16 h0, l0, h1, l1, h2, l2, h3, l3;
    split2(v.x, h0, l0); split2(v.y, h1, l1);
    split2(v.z, h2, l2); split2(v.w, h3, l3);
    uint2 ph = make_uint2(pack_bf2(h0, h1), pack_bf2(h2, h3));
    uint2 pl = make_uint2(pack_bf2(l0, l1), pack_bf2(l2, l3));
    *reinterpret_cast<uint2*>(&g_Ahi[base]) = ph;
    *reinterpret_cast<uint2*>(&g_Alo[base]) = pl;
}

// ---------------------------------------------------------------------------
// K1: main mma.sync GEMM. C[16384, 320] = Acat[16384, 3072] @ Btcat[320, 3072]^T
// Grid (2 nblk, 128 mblk). CTA tile 128x160, 8 warps (4M x 2N), warp 32x80.
// 3-stage cp.async pipeline, K-chunk=64. Epilogue: bias+relu+split / ms/us/add.
// ---------------------------------------------------------------------------
#define MAIN_STAGE 36864                      // 16KB A + 20KB B
#define SMEM_MAIN  (3 * MAIN_STAGE)

static __device__ __forceinline__ void issue_main(uint32_t sb, int ic, int st,
                                                  int m0, int nb0, int t)
{
    int seg = ic >> 4;
    int kc  = (ic & 15) * 64;
    const __nv_bfloat16 *Ap, *Bp;
    if (seg == 0)      { Ap = g_Ahi; Bp = g_Bthi; }
    else if (seg == 1) { Ap = g_Alo; Bp = g_Bthi; }
    else               { Ap = g_Ahi; Bp = g_Btlo; }
    uint32_t ab = sb + st * MAIN_STAGE;
    uint32_t bb = ab + 16384;
    #pragma unroll
    for (int l = 0; l < 4; l++) {             // A: 128 rows x 128B
        int f = t + l * 256;
        int row = f >> 3, kq = (f & 7) * 8;
        cp16(ab + SWZ(row * 128 + kq * 2), Ap + (size_t)(m0 + row) * KD + kc + kq);
    }
    #pragma unroll
    for (int l = 0; l < 5; l++) {             // B: 160 rows x 128B
        int f = t + l * 256;
        int row = f >> 3, kq = (f & 7) * 8;
        cp16(bb + SWZ(row * 128 + kq * 2), Bp + (size_t)(nb0 + row) * KD + kc + kq);
    }
}

__global__ __launch_bounds__(256, 1) void k_mma_main()
{
    extern __shared__ char smem[];
    uint32_t sb = smem_u32(smem);
    int t = threadIdx.x;
    int lane = t & 31, wid = t >> 5;
    int wm = wid & 3, wn = wid >> 2;
    int nb0 = blockIdx.x * 160;
    int m0  = blockIdx.y * 128;

    float c[2][10][4];
    #pragma unroll
    for (int i = 0; i < 2; i++)
        #pragma unroll
        for (int j = 0; j < 10; j++)
            #pragma unroll
            for (int q = 0; q < 4; q++) c[i][j][q] = 0.f;

    const int NC = 48;
    issue_main(sb, 0, 0, m0, nb0, t); CP_COMMIT();
    issue_main(sb, 1, 1, m0, nb0, t); CP_COMMIT();

    // precomputed ldmatrix sub-addresses (relative to stage base)
    int a_row = (lane & 15);
    int a_koff = (lane >> 4) * 16;
    int b_row = ((lane >> 4) & 1) * 8 + (lane & 7);
    int b_koff = ((lane >> 3) & 1) * 16;

    #pragma unroll 1
    for (int ic = 0; ic < NC; ic++) {
        __syncthreads();                       // protect stage being overwritten
        if (ic + 2 < NC) issue_main(sb, ic + 2, (ic + 2) % 3, m0, nb0, t);
        CP_COMMIT();
        CP_WAIT2();
        __syncthreads();

        uint32_t ab = sb + (ic % 3) * MAIN_STAGE;
        uint32_t bb = ab + 16384;
        #pragma unroll
        for (int ks = 0; ks < 4; ks++) {
            uint32_t a[2][4], b[10][2];
            #pragma unroll
            for (int mt = 0; mt < 2; mt++)
                LDSM4(a[mt][0], a[mt][1], a[mt][2], a[mt][3],
                      ab + SWZ((wm * 32 + mt * 16 + a_row) * 128 + ks * 32 + a_koff));
            #pragma unroll
            for (int jp = 0; jp < 5; jp++)
                LDSM4(b[2 * jp][0], b[2 * jp][1], b[2 * jp + 1][0], b[2 * jp + 1][1],
                      bb + SWZ((wn * 80 + jp * 16 + b_row) * 128 + ks * 32 + b_koff));
            #pragma unroll
            for (int mt = 0; mt < 2; mt++)
                #pragma unroll
                for (int j = 0; j < 10; j++)
                    MMA16816(c[mt][j], a[mt], b[j]);
        }
    }

    // Epilogue: accum in registers -> bias, relu, split / route.
    #pragma unroll
    for (int mt = 0; mt < 2; mt++) {
        int rbase = m0 + wm * 32 + mt * 16 + (lane >> 2);
        #pragma unroll
        for (int half = 0; half < 2; half++) {
            int m = rbase + half * 8;
            #pragma unroll
            for (int j = 0; j < 10; j++) {
                int n = nb0 + wn * 80 + j * 8 + (lane & 3) * 2;
                float v0 = c[mt][j][half * 2 + 0] + g_cbias[n];
                float v1 = c[mt][j][half * 2 + 1] + g_cbias[n + 1];
                if (n < 256) {
                    v0 = fmaxf(v0, 0.f); v1 = fmaxf(v1, 0.f);
                    __nv_bfloat16 h0, l0, h1, l1;
                    split2(v0, h0, l0); split2(v1, h1, l1);
                    *reinterpret_cast<uint32_t*>(&g_Hhi[(size_t)m * H1D + n]) = pack_bf2(h0, h1);
                    *reinterpret_cast<uint32_t*>(&g_Hlo[(size_t)m * H1D + n]) = pack_bf2(l0, l1);
                } else {
                    #pragma unroll
                    for (int e = 0; e < 2; e++) {
                        int ne = n + e;
                        float ve = e ? v1 : v0;
                        if (ne < 272)       g_MS[m * 16 + ne - 256] = ve;
                        else if (ne < 288)  g_US[m * 16 + ne - 272] = ve;
                        else if (ne == 288) g_ADD[m] = ve;
                    }
                }
            }
        }
    }
}

// ---------------------------------------------------------------------------
// K2: tail mma.sync GEMM + final reduce.
// C[16384,128] = Hcat[16384,768] @ W2tcat[128,768]^T; out = relu(.)·W3 + ...
// Grid 128 CTAs (M=128 each), 8 warps, warp tile 16x128.
// ---------------------------------------------------------------------------
#define TAIL_STAGE 32768                      // 16KB A + 16KB B
#define SMEM_TAIL  (3 * TAIL_STAGE)

static __device__ __forceinline__ void issue_tail(uint32_t sb, int ic, int st,
                                                  int m0, int t)
{
    int seg = ic >> 2;
    int kc  = (ic & 3) * 64;
    const __nv_bfloat16 *Ap, *Bp;
    if (seg == 0)      { Ap = g_Hhi;   Bp = g_W2thi; }
    else if (seg == 1) { Ap = g_Hlo;   Bp = g_W2thi; }
    else               { Ap = g_Hhi;   Bp = g_W2tlo; }
    uint32_t ab = sb + st * TAIL_STAGE;
    uint32_t bb = ab + 16384;
    #pragma unroll
    for (int l = 0; l < 4; l++) {
        int f = t + l * 256;
        int row = f >> 3, kq = (f & 7) * 8;
        cp16(ab + SWZ(row * 128 + kq * 2), Ap + (size_t)(m0 + row) * H1D + kc + kq);
    }
    #pragma unroll
    for (int l = 0; l < 4; l++) {
        int f = t + l * 256;
        int row = f >> 3, kq = (f & 7) * 8;
        cp16(bb + SWZ(row * 128 + kq * 2), Bp + (size_t)row * H1D + kc + kq);
    }
}

__global__ __launch_bounds__(256, 1) void k_mma_tail(
    const float* __restrict__ b2, const float* __restrict__ W3,
    const float* __restrict__ b3, float* __restrict__ out)
{
    extern __shared__ char smem[];
    __shared__ float b2s[128];
    __shared__ float w3s[128];
    uint32_t sb = smem_u32(smem);
    int t = threadIdx.x;
    int lane = t & 31, w = t >> 5;
    int m0 = blockIdx.x * 128;

    if (t < 128) { b2s[t] = b2[t]; w3s[t] = W3[t]; }

    float c[16][4];
    #pragma unroll
    for (int j = 0; j < 16; j++)
        #pragma unroll
        for (int q = 0; q < 4; q++) c[j][q] = 0.f;

    const int NC = 12;
    issue_tail(sb, 0, 0, m0, t); CP_COMMIT();
    issue_tail(sb, 1, 1, m0, t); CP_COMMIT();

    int a_row = (lane & 15);
    int a_koff = (lane >> 4) * 16;
    int b_row = ((lane >> 4) & 1) * 8 + (lane & 7);
    int b_koff = ((lane >> 3) & 1) * 16;

    #pragma unroll 1
    for (int ic = 0; ic < NC; ic++) {
        __syncthreads();
        if (ic + 2 < NC) issue_tail(sb, ic + 2, (ic + 2) % 3, m0, t);
        CP_COMMIT();
        CP_WAIT2();
        __syncthreads();

        uint32_t ab = sb + (ic % 3) * TAIL_STAGE;
        uint32_t bb = ab + 16384;
        #pragma unroll
        for (int ks = 0; ks < 4; ks++) {
            uint32_t a[4], b[16][2];
            LDSM4(a[0], a[1], a[2], a[3],
                  ab + SWZ((w * 16 + a_row) * 128 + ks * 32 + a_koff));
            #pragma unroll
            for (int jp = 0; jp < 8; jp++)
                LDSM4(b[2 * jp][0], b[2 * jp][1], b[2 * jp + 1][0], b[2 * jp + 1][1],
                      bb + SWZ((jp * 16 + b_row) * 128 + ks * 32 + b_koff));
            #pragma unroll
            for (int j = 0; j < 16; j++)
                MMA16816(c[j], a, b[j]);
        }
    }

    // Epilogue: relu(c + b2) dot W3, reduce across the 4 lanes sharing a row.
    float p0 = 0.f, p1 = 0.f;
    #pragma unroll
    for (int j = 0; j < 16; j++) {
        int n = j * 8 + (lane & 3) * 2;
        p0 += fmaxf(c[j][0] + b2s[n],     0.f) * w3s[n];
        p0 += fmaxf(c[j][1] + b2s[n + 1], 0.f) * w3s[n + 1];
        p1 += fmaxf(c[j][2] + b2s[n],     0.f) * w3s[n];
        p1 += fmaxf(c[j][3] + b2s[n + 1], 0.f) * w3s[n + 1];
    }
    p0 += __shfl_xor_sync(0xFFFFFFFF, p0, 1);
    p0 += __shfl_xor_sync(0xFFFFFFFF, p0, 2);
    p1 += __shfl_xor_sync(0xFFFFFFFF, p1, 1);
    p1 += __shfl_xor_sync(0xFFFFFFFF, p1, 2);

    if ((lane & 3) == 0) {
        float b3v = b3[0];
        #pragma unroll
        for (int half = 0; half < 2; half++) {
            int m = m0 + w * 16 + (lane >> 2) + half * 8;
            float s = (half ? p1 : p0) + b3v + g_ADD[m];
            #pragma unroll
            for (int i = 0; i < 16; i++) s += g_MS[m * 16 + i] * g_US[m * 16 + i];
            out[m] = s;
        }
    }
}

// ---------------------------------------------------------------------------
extern "C" void kernel_launch(void* const* d_in, const int* in_sizes, int n_in,
                              void* d_out, int out_size)
{
    const float* mv = (const float*)d_in[0];
    const float* uv = (const float*)d_in[1];
    const float* Wm = (const float*)d_in[2];
    const float* bm = (const float*)d_in[3];
    const float* Wu = (const float*)d_in[4];
    const float* bu = (const float*)d_in[5];
    const float* W1 = (const float*)d_in[6];
    const float* b1 = (const float*)d_in[7];
    const float* W2 = (const float*)d_in[8];
    const float* b2 = (const float*)d_in[9];
    const float* W3 = (const float*)d_in[10];
    const float* b3 = (const float*)d_in[11];
    float* out = (float*)d_out;

    cudaFuncSetAttribute(k_mma_main, cudaFuncAttributeMaxDynamicSharedMemorySize, SMEM_MAIN);
    cudaFuncSetAttribute(k_mma_tail, cudaFuncAttributeMaxDynamicSharedMemorySize, SMEM_TAIL);

    // Weight precompute (fresh every call).
    k_combine_gemm<<<dim3(4, 8), 256>>>(Wm, 257, W1,             256, 0,          256);
    k_combine_gemm<<<dim3(4, 8), 256>>>(Wu, 257, W1 + 256 * 256, 256, 512 * NPAD, 256);
    k_small<<<(KD * 16 + NOUT + 255) / 256, 256>>>(Wm, bm, Wu, bu, W1, b1);
    k_convB<<<(NPAD * KD + H2D * H1D + 255) / 256, 256>>>(W2);
    k_convA<<<(BATCH * KD / 4) / 256, 256>>>(mv, uv);

    // Main tensor-core (HMMA) GEMM + epilogue split.
    k_mma_main<<<dim3(2, BATCH / 128), 256, SMEM_MAIN>>>();

    // Tail tensor-core GEMM + final reduction.
    k_mma_tail<<<BATCH / 128, 256, SMEM_TAIL>>>(b2, W3, b3, out);
}

// round 6
// speedup vs baseline: 2.6567x; 1.0976x over previous
#include <cuda_runtime.h>
#include <cuda_bf16.h>
#include <cstdint>

#define BATCH 16384
#define KD    1024
#define NOUT  289
#define NPAD  320
#define H1D   256
#define H2D   128

// ---------------------------------------------------------------------------
// Device scratch (zero-initialized at load; g_Wbig pad columns stay 0 forever).
// ---------------------------------------------------------------------------
__device__ float         g_Wbig[KD * NPAD];
__device__ float         g_cbias[NPAD];
__device__ __nv_bfloat16 g_Ahi[BATCH * KD];
__device__ __nv_bfloat16 g_Alo[BATCH * KD];
__device__ __nv_bfloat16 g_Bthi[NPAD * KD];
__device__ __nv_bfloat16 g_Btlo[NPAD * KD];
__device__ __nv_bfloat16 g_Hhi[BATCH * H1D];
__device__ __nv_bfloat16 g_Hlo[BATCH * H1D];
__device__ __nv_bfloat16 g_W2thi[H2D * H1D];
__device__ __nv_bfloat16 g_W2tlo[H2D * H1D];
__device__ float         g_MS[BATCH * 16];
__device__ float         g_US[BATCH * 16];
__device__ float         g_ADD[BATCH];

// ---------------------------------------------------------------------------
// Helpers (base sm_103 PTX only: mma.sync / ldmatrix / cp.async)
// ---------------------------------------------------------------------------
static __device__ __forceinline__ uint32_t smem_u32(const void* p) {
    uint32_t a;
    asm("{ .reg .u64 t; cvta.to.shared.u64 t, %1; cvt.u32.u64 %0, t; }" : "=r"(a) : "l"(p));
    return a;
}
static __device__ __forceinline__ void cp16(uint32_t dst, const void* src) {
    asm volatile("cp.async.cg.shared.global [%0], [%1], 16;\n" :: "r"(dst), "l"(src));
}
#define CP_COMMIT() asm volatile("cp.async.commit_group;\n" ::: "memory")
#define CP_WAIT2()  asm volatile("cp.async.wait_group 2;\n" ::: "memory")

#define LDSM4(r0, r1, r2, r3, addr) \
    asm volatile("ldmatrix.sync.aligned.m8n8.x4.shared.b16 {%0,%1,%2,%3}, [%4];" \
                 : "=r"(r0), "=r"(r1), "=r"(r2), "=r"(r3) : "r"(addr))

#define MMA16816(c, a, b) \
    asm volatile("mma.sync.aligned.m16n8k16.row.col.f32.bf16.bf16.f32 " \
                 "{%0,%1,%2,%3},{%4,%5,%6,%7},{%8,%9},{%0,%1,%2,%3};" \
                 : "+f"((c)[0]), "+f"((c)[1]), "+f"((c)[2]), "+f"((c)[3]) \
                 : "r"((a)[0]), "r"((a)[1]), "r"((a)[2]), "r"((a)[3]), \
                   "r"((b)[0]), "r"((b)[1]))

#define SWZ(x) ((x) ^ (((x) >> 3) & 0x70))

static __device__ __forceinline__ void split2(float v, __nv_bfloat16& h, __nv_bfloat16& l) {
    h = __float2bfloat16(v);
    l = __float2bfloat16(v - __bfloat162float(h));
}
static __device__ __forceinline__ uint32_t pack_bf2(__nv_bfloat16 a, __nv_bfloat16 b) {
    __nv_bfloat162 p; p.x = a; p.y = b;
    return *reinterpret_cast<uint32_t*>(&p);
}

// ---------------------------------------------------------------------------
// K0a: Wbig[:, :256] = Wm[:, :256] @ W1[:256] + Wu part, fp32 tiled.
// blockIdx.z selects the (tower, W1 half) pair; single launch.
// ---------------------------------------------------------------------------
__global__ __launch_bounds__(256) void k_combine_gemm(
    const float* __restrict__ Wm, const float* __restrict__ Wu,
    const float* __restrict__ W1)
{
    const float* A  = (blockIdx.z == 0) ? Wm : Wu;
    const float* Bw = (blockIdx.z == 0) ? W1 : (W1 + 256 * 256);
    int c_offset    = (blockIdx.z == 0) ? 0  : 512 * NPAD;
    const int lda = 257, ldb = 256, K = 256;

    __shared__ float As[16][64];
    __shared__ float Bs[16][64];
    int t = threadIdx.x;
    int tx = t & 15, ty = t >> 4;
    int m0 = blockIdx.y * 64, n0 = blockIdx.x * 64;
    float acc[4][4] = {};

    for (int k0 = 0; k0 < K; k0 += 16) {
        {
            int row = t >> 2;
            int kq = (t & 3) << 2;
            const float* ap = A + (m0 + row) * lda + k0 + kq;
            #pragma unroll
            for (int i = 0; i < 4; i++) As[kq + i][row] = ap[i];
        }
        {
            int kr = t >> 4;
            int nq = (t & 15) << 2;
            float4 v = *reinterpret_cast<const float4*>(Bw + (k0 + kr) * ldb + n0 + nq);
            *reinterpret_cast<float4*>(&Bs[kr][nq]) = v;
        }
        __syncthreads();
        #pragma unroll
        for (int kk = 0; kk < 16; kk++) {
            float a[4], b[4];
            #pragma unroll
            for (int i = 0; i < 4; i++) a[i] = As[kk][ty * 4 + i];
            #pragma unroll
            for (int j = 0; j < 4; j++) b[j] = Bs[kk][tx * 4 + j];
            #pragma unroll
            for (int i = 0; i < 4; i++)
                #pragma unroll
                for (int j = 0; j < 4; j++) acc[i][j] += a[i] * b[j];
        }
        __syncthreads();
    }
    #pragma unroll
    for (int i = 0; i < 4; i++)
        #pragma unroll
        for (int j = 0; j < 4; j++)
            g_Wbig[c_offset + (m0 + ty * 4 + i) * NPAD + n0 + tx * 4 + j] = acc[i][j];
}

// ---------------------------------------------------------------------------
// K0b: ms/us/additive weight columns of Wbig + combined bias vector.
// ---------------------------------------------------------------------------
__global__ void k_small(const float* __restrict__ Wm, const float* __restrict__ bm,
                        const float* __restrict__ Wu, const float* __restrict__ bu,
                        const float* __restrict__ W1, const float* __restrict__ b1)
{
    int t = blockIdx.x * blockDim.x + threadIdx.x;
    if (t < KD * 16) {
        int k = t >> 4, d = t & 15;
        float s = 0.f;
        if (k < 512) {
            #pragma unroll
            for (int i = 0; i < 16; i++) s += Wm[k * 257 + i * 16 + d];
            g_Wbig[k * NPAD + 256 + d] = s;
            if (d == 0) g_Wbig[k * NPAD + 288] = Wm[k * 257 + 256];
        } else {
            int ku = k - 512;
            #pragma unroll
            for (int i = 0; i < 16; i++) s += Wu[ku * 257 + i * 16 + d];
            g_Wbig[k * NPAD + 272 + d] = s;
            if (d == 0) g_Wbig[k * NPAD + 288] = Wu[ku * 257 + 256];
        }
        return;
    }
    int c = t - KD * 16;
    if (c >= 0 && c < NOUT) {
        float v;
        if (c < 256) {
            v = b1[c];
            for (int j = 0; j < 256; j++) v += bm[j] * W1[j * 256 + c];
            for (int j = 0; j < 256; j++) v += bu[j] * W1[(256 + j) * 256 + c];
        } else if (c < 272) {
            int d = c - 256; v = 0.f;
            #pragma unroll
            for (int i = 0; i < 16; i++) v += bm[i * 16 + d];
        } else if (c < 288) {
            int d = c - 272; v = 0.f;
            #pragma unroll
            for (int i = 0; i < 16; i++) v += bu[i * 16 + d];
        } else {
            v = bm[256] + bu[256];
        }
        g_cbias[c] = v;
    }
}

// ---------------------------------------------------------------------------
// K0c: transpose+split Wbig -> Bt(hi/lo) [NPAD rows, KD k-major]; also W2 -> W2t.
// ---------------------------------------------------------------------------
__global__ void k_convB(const float* __restrict__ W2)
{
    int i = blockIdx.x * blockDim.x + threadIdx.x;
    if (i < NPAD * KD) {
        int n = i >> 10, k = i & 1023;
        __nv_bfloat16 h, l;
        split2(g_Wbig[k * NPAD + n], h, l);
        g_Bthi[i] = h; g_Btlo[i] = l;
        return;
    }
    int j = i - NPAD * KD;
    if (j < H2D * H1D) {
        int r = j >> 8, c = j & 255;          // W2t[r][c] = W2[c][r]
        __nv_bfloat16 h, l;
        split2(W2[c * H2D + r], h, l);
        g_W2thi[j] = h; g_W2tlo[j] = l;
    }
}

// ---------------------------------------------------------------------------
// K0d: split inputs -> Ahi/Alo bf16 [BATCH, 1024] (mv cols 0..511, uv 512..1023)
// ---------------------------------------------------------------------------
__global__ __launch_bounds__(256) void k_convA(const float* __restrict__ mv,
                                               const float* __restrict__ uv)
{
    int i = blockIdx.x * blockDim.x + threadIdx.x;   // one per 4 elems
    int base = i * 4;
    int row = base >> 10, k = base & 1023;
    const float* src = (k < 512) ? (mv + (size_t)row * 512 + k)
                                 : (uv + (size_t)row * 512 + k - 512);
    float4 v = *reinterpret_cast<const float4*>(src);
    __nv_bfloat16 h0, l0, h1, l1, h2, l2, h3, l3;
    split2(v.x, h0, l0); split2(v.y, h1, l1);
    split2(v.z, h2, l2); split2(v.w, h3, l3);
    uint2 ph = make_uint2(pack_bf2(h0, h1), pack_bf2(h2, h3));
    uint2 pl = make_uint2(pack_bf2(l0, l1), pack_bf2(l2, l3));
    *reinterpret_cast<uint2*>(&g_Ahi[base]) = ph;
    *reinterpret_cast<uint2*>(&g_Alo[base]) = pl;
}

// ---------------------------------------------------------------------------
// K1: main mma.sync GEMM. C[16384, 320] = Acat[16384, 3072] @ Btcat[320, 3072]^T
// 128 CTAs (one wave), CTA tile 128x320, 512 thr (16 warps, 4M x 4N, warp 32x80).
// 3-stage cp.async pipeline, K-chunk=64. Epilogue: bias+relu+split / ms/us/add.
// ---------------------------------------------------------------------------
#define MAIN_STAGE 57344                      // 16KB A + 40KB B
#define SMEM_MAIN  (3 * MAIN_STAGE)           // 168KB

static __device__ __forceinline__ void issue_main(uint32_t sb, int ic, int st,
                                                  int m0, int t)
{
    int seg = ic >> 4;
    int kc  = (ic & 15) * 64;
    const __nv_bfloat16 *Ap, *Bp;
    if (seg == 0)      { Ap = g_Ahi; Bp = g_Bthi; }
    else if (seg == 1) { Ap = g_Alo; Bp = g_Bthi; }
    else               { Ap = g_Ahi; Bp = g_Btlo; }
    uint32_t ab = sb + st * MAIN_STAGE;
    uint32_t bb = ab + 16384;
    #pragma unroll
    for (int l = 0; l < 2; l++) {             // A: 128 rows x 128B
        int f = t + l * 512;
        int row = f >> 3, kq = (f & 7) * 8;
        cp16(ab + SWZ(row * 128 + kq * 2), Ap + (size_t)(m0 + row) * KD + kc + kq);
    }
    #pragma unroll
    for (int l = 0; l < 5; l++) {             // B: 320 rows x 128B
        int f = t + l * 512;
        int row = f >> 3, kq = (f & 7) * 8;
        cp16(bb + SWZ(row * 128 + kq * 2), Bp + (size_t)row * KD + kc + kq);
    }
}

__global__ __launch_bounds__(512, 1) void k_mma_main()
{
    extern __shared__ char smem[];
    uint32_t sb = smem_u32(smem);
    int t = threadIdx.x;
    int lane = t & 31, wid = t >> 5;
    int wm = wid & 3, wn = wid >> 2;          // 4M x 4N warps
    int m0 = blockIdx.x * 128;

    float c[2][10][4];
    #pragma unroll
    for (int i = 0; i < 2; i++)
        #pragma unroll
        for (int j = 0; j < 10; j++)
            #pragma unroll
            for (int q = 0; q < 4; q++) c[i][j][q] = 0.f;

    const int NC = 48;
    issue_main(sb, 0, 0, m0, t); CP_COMMIT();
    issue_main(sb, 1, 1, m0, t); CP_COMMIT();

    int a_row  = (lane & 15);
    int a_koff = (lane >> 4) * 16;
    int b_row  = ((lane >> 4) & 1) * 8 + (lane & 7);
    int b_koff = ((lane >> 3) & 1) * 16;

    #pragma unroll 1
    for (int ic = 0; ic < NC; ic++) {
        __syncthreads();                       // stage (ic+2)%3 free of readers
        if (ic + 2 < NC) issue_main(sb, ic + 2, (ic + 2) % 3, m0, t);
        CP_COMMIT();
        CP_WAIT2();
        __syncthreads();

        uint32_t ab = sb + (ic % 3) * MAIN_STAGE;
        uint32_t bb = ab + 16384;
        #pragma unroll
        for (int ks = 0; ks < 4; ks++) {
            uint32_t a[2][4], b[10][2];
            #pragma unroll
            for (int mt = 0; mt < 2; mt++)
                LDSM4(a[mt][0], a[mt][1], a[mt][2], a[mt][3],
                      ab + SWZ((wm * 32 + mt * 16 + a_row) * 128 + ks * 32 + a_koff));
            #pragma unroll
            for (int jp = 0; jp < 5; jp++)
                LDSM4(b[2 * jp][0], b[2 * jp][1], b[2 * jp + 1][0], b[2 * jp + 1][1],
                      bb + SWZ((wn * 80 + jp * 16 + b_row) * 128 + ks * 32 + b_koff));
            #pragma unroll
            for (int mt = 0; mt < 2; mt++)
                #pragma unroll
                for (int j = 0; j < 10; j++)
                    MMA16816(c[mt][j], a[mt], b[j]);
        }
    }

    // Epilogue: bias, relu, split / route.
    #pragma unroll
    for (int mt = 0; mt < 2; mt++) {
        int rbase = m0 + wm * 32 + mt * 16 + (lane >> 2);
        #pragma unroll
        for (int half = 0; half < 2; half++) {
            int m = rbase + half * 8;
            #pragma unroll
            for (int j = 0; j < 10; j++) {
                int n = wn * 80 + j * 8 + (lane & 3) * 2;
                float v0 = c[mt][j][half * 2 + 0] + g_cbias[n];
                float v1 = c[mt][j][half * 2 + 1] + g_cbias[n + 1];
                if (n < 256) {
                    v0 = fmaxf(v0, 0.f); v1 = fmaxf(v1, 0.f);
                    __nv_bfloat16 h0, l0, h1, l1;
                    split2(v0, h0, l0); split2(v1, h1, l1);
                    *reinterpret_cast<uint32_t*>(&g_Hhi[(size_t)m * H1D + n]) = pack_bf2(h0, h1);
                    *reinterpret_cast<uint32_t*>(&g_Hlo[(size_t)m * H1D + n]) = pack_bf2(l0, l1);
                } else {
                    #pragma unroll
                    for (int e = 0; e < 2; e++) {
                        int ne = n + e;
                        float ve = e ? v1 : v0;
                        if (ne < 272)       g_MS[m * 16 + ne - 256] = ve;
                        else if (ne < 288)  g_US[m * 16 + ne - 272] = ve;
                        else if (ne == 288) g_ADD[m] = ve;
                    }
                }
            }
        }
    }
}

// ---------------------------------------------------------------------------
// K2: tail mma.sync GEMM + final reduce.
// C[16384,128] = Hcat[16384,768] @ W2tcat[128,768]^T; out = relu(.)·W3 + ...
// Grid 128 CTAs (M=128 each), 8 warps, warp tile 16x128.
// ---------------------------------------------------------------------------
#define TAIL_STAGE 32768                      // 16KB A + 16KB B
#define SMEM_TAIL  (3 * TAIL_STAGE)

static __device__ __forceinline__ void issue_tail(uint32_t sb, int ic, int st,
                                                  int m0, int t)
{
    int seg = ic >> 2;
    int kc  = (ic & 3) * 64;
    const __nv_bfloat16 *Ap, *Bp;
    if (seg == 0)      { Ap = g_Hhi;   Bp = g_W2thi; }
    else if (seg == 1) { Ap = g_Hlo;   Bp = g_W2thi; }
    else               { Ap = g_Hhi;   Bp = g_W2tlo; }
    uint32_t ab = sb + st * TAIL_STAGE;
    uint32_t bb = ab + 16384;
    #pragma unroll
    for (int l = 0; l < 4; l++) {
        int f = t + l * 256;
        int row = f >> 3, kq = (f & 7) * 8;
        cp16(ab + SWZ(row * 128 + kq * 2), Ap + (size_t)(m0 + row) * H1D + kc + kq);
    }
    #pragma unroll
    for (int l = 0; l < 4; l++) {
        int f = t + l * 256;
        int row = f >> 3, kq = (f & 7) * 8;
        cp16(bb + SWZ(row * 128 + kq * 2), Bp + (size_t)row * H1D + kc + kq);
    }
}

__global__ __launch_bounds__(256, 1) void k_mma_tail(
    const float* __restrict__ b2, const float* __restrict__ W3,
    const float* __restrict__ b3, float* __restrict__ out)
{
    extern __shared__ char smem[];
    __shared__ float b2s[128];
    __shared__ float w3s[128];
    uint32_t sb = smem_u32(smem);
    int t = threadIdx.x;
    int lane = t & 31, w = t >> 5;
    int m0 = blockIdx.x * 128;

    if (t < 128) { b2s[t] = b2[t]; w3s[t] = W3[t]; }

    float c[16][4];
    #pragma unroll
    for (int j = 0; j < 16; j++)
        #pragma unroll
        for (int q = 0; q < 4; q++) c[j][q] = 0.f;

    const int NC = 12;
    issue_tail(sb, 0, 0, m0, t); CP_COMMIT();
    issue_tail(sb, 1, 1, m0, t); CP_COMMIT();

    int a_row  = (lane & 15);
    int a_koff = (lane >> 4) * 16;
    int b_row  = ((lane >> 4) & 1) * 8 + (lane & 7);
    int b_koff = ((lane >> 3) & 1) * 16;

    #pragma unroll 1
    for (int ic = 0; ic < NC; ic++) {
        __syncthreads();
        if (ic + 2 < NC) issue_tail(sb, ic + 2, (ic + 2) % 3, m0, t);
        CP_COMMIT();
        CP_WAIT2();
        __syncthreads();

        uint32_t ab = sb + (ic % 3) * TAIL_STAGE;
        uint32_t bb = ab + 16384;
        #pragma unroll
        for (int ks = 0; ks < 4; ks++) {
            uint32_t a[4], b[16][2];
            LDSM4(a[0], a[1], a[2], a[3],
                  ab + SWZ((w * 16 + a_row) * 128 + ks * 32 + a_koff));
            #pragma unroll
            for (int jp = 0; jp < 8; jp++)
                LDSM4(b[2 * jp][0], b[2 * jp][1], b[2 * jp + 1][0], b[2 * jp + 1][1],
                      bb + SWZ((jp * 16 + b_row) * 128 + ks * 32 + b_koff));
            #pragma unroll
            for (int j = 0; j < 16; j++)
                MMA16816(c[j], a, b[j]);
        }
    }

    // Epilogue: relu(c + b2) dot W3, reduce across the 4 lanes sharing a row.
    float p0 = 0.f, p1 = 0.f;
    #pragma unroll
    for (int j = 0; j < 16; j++) {
        int n = j * 8 + (lane & 3) * 2;
        p0 += fmaxf(c[j][0] + b2s[n],     0.f) * w3s[n];
        p0 += fmaxf(c[j][1] + b2s[n + 1], 0.f) * w3s[n + 1];
        p1 += fmaxf(c[j][2] + b2s[n],     0.f) * w3s[n];
        p1 += fmaxf(c[j][3] + b2s[n + 1], 0.f) * w3s[n + 1];
    }
    p0 += __shfl_xor_sync(0xFFFFFFFF, p0, 1);
    p0 += __shfl_xor_sync(0xFFFFFFFF, p0, 2);
    p1 += __shfl_xor_sync(0xFFFFFFFF, p1, 1);
    p1 += __shfl_xor_sync(0xFFFFFFFF, p1, 2);

    if ((lane & 3) == 0) {
        float b3v = b3[0];
        #pragma unroll
        for (int half = 0; half < 2; half++) {
            int m = m0 + w * 16 + (lane >> 2) + half * 8;
            float s = (half ? p1 : p0) + b3v + g_ADD[m];
            #pragma unroll
            for (int i = 0; i < 16; i++) s += g_MS[m * 16 + i] * g_US[m * 16 + i];
            out[m] = s;
        }
    }
}

// ---------------------------------------------------------------------------
extern "C" void kernel_launch(void* const* d_in, const int* in_sizes, int n_in,
                              void* d_out, int out_size)
{
    const float* mv = (const float*)d_in[0];
    const float* uv = (const float*)d_in[1];
    const float* Wm = (const float*)d_in[2];
    const float* bm = (const float*)d_in[3];
    const float* Wu = (const float*)d_in[4];
    const float* bu = (const float*)d_in[5];
    const float* W1 = (const float*)d_in[6];
    const float* b1 = (const float*)d_in[7];
    const float* W2 = (const float*)d_in[8];
    const float* b2 = (const float*)d_in[9];
    const float* W3 = (const float*)d_in[10];
    const float* b3 = (const float*)d_in[11];
    float* out = (float*)d_out;

    cudaFuncSetAttribute(k_mma_main, cudaFuncAttributeMaxDynamicSharedMemorySize, SMEM_MAIN);
    cudaFuncSetAttribute(k_mma_tail, cudaFuncAttributeMaxDynamicSharedMemorySize, SMEM_TAIL);

    // Weight precompute (fresh every call).
    k_combine_gemm<<<dim3(4, 8, 2), 256>>>(Wm, Wu, W1);
    k_small<<<(KD * 16 + NOUT + 255) / 256, 256>>>(Wm, bm, Wu, bu, W1, b1);
    k_convB<<<(NPAD * KD + H2D * H1D + 255) / 256, 256>>>(W2);
    k_convA<<<(BATCH * KD / 4) / 256, 256>>>(mv, uv);

    // Main tensor-core (HMMA) GEMM + epilogue split. One wave of 128 CTAs.
    k_mma_main<<<BATCH / 128, 512, SMEM_MAIN>>>();

    // Tail tensor-core GEMM + final reduction.
    k_mma_tail<<<BATCH / 128, 256, SMEM_TAIL>>>(b2, W3, b3, out);
}

// round 7
// speedup vs baseline: 2.7640x; 1.0404x over previous
#include <cuda_runtime.h>
#include <cuda_bf16.h>
#include <cstdint>

#define BATCH 16384
#define KD    1024
#define NOUT  289
#define NPAD  320
#define H1D   256
#define H2D   128

// ---------------------------------------------------------------------------
// Device scratch (zero-initialized at load; g_Wbig pad columns stay 0 forever).
// ---------------------------------------------------------------------------
__device__ float         g_Wbig[KD * NPAD];
__device__ float         g_cbias[NPAD];
__device__ __nv_bfloat16 g_Bthi[NPAD * KD];
__device__ __nv_bfloat16 g_Btlo[NPAD * KD];
__device__ __nv_bfloat16 g_Hhi[BATCH * H1D];
__device__ __nv_bfloat16 g_Hlo[BATCH * H1D];
__device__ __nv_bfloat16 g_W2thi[H2D * H1D];
__device__ __nv_bfloat16 g_W2tlo[H2D * H1D];
__device__ float         g_MS[BATCH * 16];
__device__ float         g_US[BATCH * 16];
__device__ float         g_ADD[BATCH];

// ---------------------------------------------------------------------------
// Helpers (base sm_103 PTX only: mma.sync / ldmatrix / cp.async)
// ---------------------------------------------------------------------------
static __device__ __forceinline__ uint32_t smem_u32(const void* p) {
    uint32_t a;
    asm("{ .reg .u64 t; cvta.to.shared.u64 t, %1; cvt.u32.u64 %0, t; }" : "=r"(a) : "l"(p));
    return a;
}
static __device__ __forceinline__ void cp16(uint32_t dst, const void* src) {
    asm volatile("cp.async.cg.shared.global [%0], [%1], 16;\n" :: "r"(dst), "l"(src));
}
#define CP_COMMIT() asm volatile("cp.async.commit_group;\n" ::: "memory")
#define CP_WAIT1()  asm volatile("cp.async.wait_group 1;\n" ::: "memory")
#define CP_WAIT2()  asm volatile("cp.async.wait_group 2;\n" ::: "memory")

#define LDSM4(r0, r1, r2, r3, addr) \
    asm volatile("ldmatrix.sync.aligned.m8n8.x4.shared.b16 {%0,%1,%2,%3}, [%4];" \
                 : "=r"(r0), "=r"(r1), "=r"(r2), "=r"(r3) : "r"(addr))

#define MMA16816(c, a, b) \
    asm volatile("mma.sync.aligned.m16n8k16.row.col.f32.bf16.bf16.f32 " \
                 "{%0,%1,%2,%3},{%4,%5,%6,%7},{%8,%9},{%0,%1,%2,%3};" \
                 : "+f"((c)[0]), "+f"((c)[1]), "+f"((c)[2]), "+f"((c)[3]) \
                 : "r"((a)[0]), "r"((a)[1]), "r"((a)[2]), "r"((a)[3]), \
                   "r"((b)[0]), "r"((b)[1]))

#define SWZ(x)   ((x) ^ (((x) >> 3) & 0x70))   // 128B-row swizzle (tail)
#define SWZ64(x) ((x) ^ (((x) >> 3) & 0x30))   // 64B-row swizzle (main, CK=32)

static __device__ __forceinline__ void split2(float v, __nv_bfloat16& h, __nv_bfloat16& l) {
    h = __float2bfloat16(v);
    l = __float2bfloat16(v - __bfloat162float(h));
}
static __device__ __forceinline__ uint32_t pack_bf2(__nv_bfloat16 a, __nv_bfloat16 b) {
    __nv_bfloat162 p; p.x = a; p.y = b;
    return *reinterpret_cast<uint32_t*>(&p);
}

// ---------------------------------------------------------------------------
// K0a: Wbig[:, :256] = Wm[:, :256] @ W1[:256] + Wu part, fp32 tiled.
// blockIdx.z selects the (tower, W1 half) pair; single launch.
// ---------------------------------------------------------------------------
__global__ __launch_bounds__(256) void k_combine_gemm(
    const float* __restrict__ Wm, const float* __restrict__ Wu,
    const float* __restrict__ W1)
{
    const float* A  = (blockIdx.z == 0) ? Wm : Wu;
    const float* Bw = (blockIdx.z == 0) ? W1 : (W1 + 256 * 256);
    int c_offset    = (blockIdx.z == 0) ? 0  : 512 * NPAD;
    const int lda = 257, ldb = 256, K = 256;

    __shared__ float As[16][64];
    __shared__ float Bs[16][64];
    int t = threadIdx.x;
    int tx = t & 15, ty = t >> 4;
    int m0 = blockIdx.y * 64, n0 = blockIdx.x * 64;
    float acc[4][4] = {};

    for (int k0 = 0; k0 < K; k0 += 16) {
        {
            int row = t >> 2;
            int kq = (t & 3) << 2;
            const float* ap = A + (m0 + row) * lda + k0 + kq;
            #pragma unroll
            for (int i = 0; i < 4; i++) As[kq + i][row] = ap[i];
        }
        {
            int kr = t >> 4;
            int nq = (t & 15) << 2;
            float4 v = *reinterpret_cast<const float4*>(Bw + (k0 + kr) * ldb + n0 + nq);
            *reinterpret_cast<float4*>(&Bs[kr][nq]) = v;
        }
        __syncthreads();
        #pragma unroll
        for (int kk = 0; kk < 16; kk++) {
            float a[4], b[4];
            #pragma unroll
            for (int i = 0; i < 4; i++) a[i] = As[kk][ty * 4 + i];
            #pragma unroll
            for (int j = 0; j < 4; j++) b[j] = Bs[kk][tx * 4 + j];
            #pragma unroll
            for (int i = 0; i < 4; i++)
                #pragma unroll
                for (int j = 0; j < 4; j++) acc[i][j] += a[i] * b[j];
        }
        __syncthreads();
    }
    #pragma unroll
    for (int i = 0; i < 4; i++)
        #pragma unroll
        for (int j = 0; j < 4; j++)
            g_Wbig[c_offset + (m0 + ty * 4 + i) * NPAD + n0 + tx * 4 + j] = acc[i][j];
}

// ---------------------------------------------------------------------------
// K0b: ms/us/additive weight columns of Wbig + combined bias vector.
// ---------------------------------------------------------------------------
__global__ void k_small(const float* __restrict__ Wm, const float* __restrict__ bm,
                        const float* __restrict__ Wu, const float* __restrict__ bu,
                        const float* __restrict__ W1, const float* __restrict__ b1)
{
    int t = blockIdx.x * blockDim.x + threadIdx.x;
    if (t < KD * 16) {
        int k = t >> 4, d = t & 15;
        float s = 0.f;
        if (k < 512) {
            #pragma unroll
            for (int i = 0; i < 16; i++) s += Wm[k * 257 + i * 16 + d];
            g_Wbig[k * NPAD + 256 + d] = s;
            if (d == 0) g_Wbig[k * NPAD + 288] = Wm[k * 257 + 256];
        } else {
            int ku = k - 512;
            #pragma unroll
            for (int i = 0; i < 16; i++) s += Wu[ku * 257 + i * 16 + d];
            g_Wbig[k * NPAD + 272 + d] = s;
            if (d == 0) g_Wbig[k * NPAD + 288] = Wu[ku * 257 + 256];
        }
        return;
    }
    int c = t - KD * 16;
    if (c >= 0 && c < NOUT) {
        float v;
        if (c < 256) {
            v = b1[c];
            for (int j = 0; j < 256; j++) v += bm[j] * W1[j * 256 + c];
            for (int j = 0; j < 256; j++) v += bu[j] * W1[(256 + j) * 256 + c];
        } else if (c < 272) {
            int d = c - 256; v = 0.f;
            #pragma unroll
            for (int i = 0; i < 16; i++) v += bm[i * 16 + d];
        } else if (c < 288) {
            int d = c - 272; v = 0.f;
            #pragma unroll
            for (int i = 0; i < 16; i++) v += bu[i * 16 + d];
        } else {
            v = bm[256] + bu[256];
        }
        g_cbias[c] = v;
    }
}

// ---------------------------------------------------------------------------
// K0c: transpose+split Wbig -> Bt(hi/lo) [NPAD rows, KD k-major]; also W2 -> W2t.
// ---------------------------------------------------------------------------
__global__ void k_convB(const float* __restrict__ W2)
{
    int i = blockIdx.x * blockDim.x + threadIdx.x;
    if (i < NPAD * KD) {
        int n = i >> 10, k = i & 1023;
        __nv_bfloat16 h, l;
        split2(g_Wbig[k * NPAD + n], h, l);
        g_Bthi[i] = h; g_Btlo[i] = l;
        return;
    }
    int j = i - NPAD * KD;
    if (j < H2D * H1D) {
        int r = j >> 8, c = j & 255;          // W2t[r][c] = W2[c][r]
        __nv_bfloat16 h, l;
        split2(W2[c * H2D + r], h, l);
        g_W2thi[j] = h; g_W2tlo[j] = l;
    }
}

// ---------------------------------------------------------------------------
// K1: main mma.sync GEMM with fused fp32->bf16 hi/lo split of A.
// C[16384, 320] = A[16384, 1024(fp32)] (x) Bt(hi/lo)[320, 1024]^T, 3 split terms.
// 128 CTAs (one wave), 512 thr (16 warps, 4M x 4N, warp 32x80), K-chunk=32,
// 3-stage pipeline: B via cp.async, A via LDG fp32 -> register split -> STS bf16.
// ---------------------------------------------------------------------------
#define CK         32
#define NCHUNK     32
#define AHI_OFF    0
#define ALO_OFF    8192
#define BHI_OFF    16384
#define BLO_OFF    36864
#define MAIN_STAGE 57344                      // 8+8+20+20 KB
#define SMEM_MAIN  (3 * MAIN_STAGE)           // 168 KB

static __device__ __forceinline__ void ldg_a(float4* p, int ch, int m0, int t,
                                             const float* __restrict__ mv,
                                             const float* __restrict__ uv)
{
    int kc = ch * CK;
    const float* base = (kc < 512) ? (mv + kc) : (uv + kc - 512);
    #pragma unroll
    for (int l = 0; l < 2; l++) {
        int f = t + l * 512;
        int row = f >> 3, q = f & 7;
        p[l] = *reinterpret_cast<const float4*>(base + (size_t)(m0 + row) * 512 + q * 4);
    }
}

static __device__ __forceinline__ void sts_a(const float4* p, uint32_t stg, int t)
{
    #pragma unroll
    for (int l = 0; l < 2; l++) {
        int f = t + l * 512;
        int row = f >> 3, q = f & 7;
        __nv_bfloat16 h0, l0, h1, l1, h2, l2, h3, l3;
        split2(p[l].x, h0, l0); split2(p[l].y, h1, l1);
        split2(p[l].z, h2, l2); split2(p[l].w, h3, l3);
        uint32_t hi0 = pack_bf2(h0, h1), hi1 = pack_bf2(h2, h3);
        uint32_t lo0 = pack_bf2(l0, l1), lo1 = pack_bf2(l2, l3);
        uint32_t off = SWZ64(row * 64 + q * 8);
        asm volatile("st.shared.v2.b32 [%0], {%1,%2};"
                     :: "r"(stg + AHI_OFF + off), "r"(hi0), "r"(hi1) : "memory");
        asm volatile("st.shared.v2.b32 [%0], {%1,%2};"
                     :: "r"(stg + ALO_OFF + off), "r"(lo0), "r"(lo1) : "memory");
    }
}

static __device__ __forceinline__ void cp_b(uint32_t stg, int ch, int t)
{
    int kc = ch * CK;
    #pragma unroll
    for (int l = 0; l < 5; l++) {
        int f = t + l * 512;                  // 0..2559: 1280 hi + 1280 lo units
        int lobuf = f >= 1280;
        int fr = lobuf ? f - 1280 : f;
        int row = fr >> 2, u = fr & 3;
        const __nv_bfloat16* src = (lobuf ? g_Btlo : g_Bthi) + (size_t)row * KD + kc + u * 8;
        cp16(stg + (lobuf ? BLO_OFF : BHI_OFF) + SWZ64(row * 64 + u * 16), src);
    }
}

static __device__ __forceinline__ void seg_mma(uint32_t ab, uint32_t bb, int ks,
                                               int wm, int wn,
                                               int a_row, int a_koff,
                                               int b_row, int b_koff,
                                               float c[2][10][4])
{
    uint32_t a[2][4];
    #pragma unroll
    for (int mt = 0; mt < 2; mt++)
        LDSM4(a[mt][0], a[mt][1], a[mt][2], a[mt][3],
              ab + SWZ64((wm * 32 + mt * 16 + a_row) * 64 + ks * 32 + a_koff));
    #pragma unroll
    for (int jp = 0; jp < 5; jp++) {
        uint32_t b0[2], b1[2];
        LDSM4(b0[0], b0[1], b1[0], b1[1],
              bb + SWZ64((wn * 80 + jp * 16 + b_row) * 64 + ks * 32 + b_koff));
        #pragma unroll
        for (int mt = 0; mt < 2; mt++) {
            MMA16816(c[mt][2 * jp],     a[mt], b0);
            MMA16816(c[mt][2 * jp + 1], a[mt], b1);
        }
    }
}

__global__ __launch_bounds__(512, 1) void k_mma_main(
    const float* __restrict__ mv, const float* __restrict__ uv)
{
    extern __shared__ char smem[];
    uint32_t sb = smem_u32(smem);
    int t = threadIdx.x;
    int lane = t & 31, wid = t >> 5;
    int wm = wid & 3, wn = wid >> 2;          // 4M x 4N warps
    int m0 = blockIdx.x * 128;

    float c[2][10][4];
    #pragma unroll
    for (int i = 0; i < 2; i++)
        #pragma unroll
        for (int j = 0; j < 10; j++)
            #pragma unroll
            for (int q = 0; q < 4; q++) c[i][j][q] = 0.f;

    int a_row  = (lane & 15);
    int a_koff = (lane >> 4) * 16;
    int b_row  = ((lane >> 4) & 1) * 8 + (lane & 7);
    int b_koff = ((lane >> 3) & 1) * 16;

    // Prologue: chunks 0,1 (A via LDG+split+STS, B via cp.async).
    {
        float4 q0[2], q1[2];
        ldg_a(q0, 0, m0, t, mv, uv);
        ldg_a(q1, 1, m0, t, mv, uv);
        cp_b(sb + 0 * MAIN_STAGE, 0, t); CP_COMMIT();
        cp_b(sb + 1 * MAIN_STAGE, 1, t); CP_COMMIT();
        sts_a(q0, sb + 0 * MAIN_STAGE, t);
        sts_a(q1, sb + 1 * MAIN_STAGE, t);
    }

    float4 pf[2];
    #pragma unroll 1
    for (int ic = 0; ic < NCHUNK; ic++) {
        bool pfv = (ic + 2 < NCHUNK);
        if (pfv) ldg_a(pf, ic + 2, m0, t, mv, uv);   // latency hidden by mma below
        CP_WAIT1();                                   // my B(ic) group arrived
        __syncthreads();                              // all threads' data visible;
                                                      // stage (ic+2)%3 readers done
        if (pfv) cp_b(sb + ((ic + 2) % 3) * MAIN_STAGE, ic + 2, t);
        CP_COMMIT();                                  // (empty group when !pfv)

        uint32_t stg = sb + (ic % 3) * MAIN_STAGE;
        // ks = 0: three split terms
        seg_mma(stg + AHI_OFF, stg + BHI_OFF, 0, wm, wn, a_row, a_koff, b_row, b_koff, c);
        seg_mma(stg + ALO_OFF, stg + BHI_OFF, 0, wm, wn, a_row, a_koff, b_row, b_koff, c);
        seg_mma(stg + AHI_OFF, stg + BLO_OFF, 0, wm, wn, a_row, a_koff, b_row, b_koff, c);
        if (pfv) sts_a(pf, sb + ((ic + 2) % 3) * MAIN_STAGE, t);
        // ks = 1
        seg_mma(stg + AHI_OFF, stg + BHI_OFF, 1, wm, wn, a_row, a_koff, b_row, b_koff, c);
        seg_mma(stg + ALO_OFF, stg + BHI_OFF, 1, wm, wn, a_row, a_koff, b_row, b_koff, c);
        seg_mma(stg + AHI_OFF, stg + BLO_OFF, 1, wm, wn, a_row, a_koff, b_row, b_koff, c);
    }

    // Epilogue: bias, relu, split / route.
    #pragma unroll
    for (int mt = 0; mt < 2; mt++) {
        int rbase = m0 + wm * 32 + mt * 16 + (lane >> 2);
        #pragma unroll
        for (int half = 0; half < 2; half++) {
            int m = rbase + half * 8;
            #pragma unroll
            for (int j = 0; j < 10; j++) {
                int n = wn * 80 + j * 8 + (lane & 3) * 2;
                float v0 = c[mt][j][half * 2 + 0] + g_cbias[n];
                float v1 = c[mt][j][half * 2 + 1] + g_cbias[n + 1];
                if (n < 256) {
                    v0 = fmaxf(v0, 0.f); v1 = fmaxf(v1, 0.f);
                    __nv_bfloat16 h0, l0, h1, l1;
                    split2(v0, h0, l0); split2(v1, h1, l1);
                    *reinterpret_cast<uint32_t*>(&g_Hhi[(size_t)m * H1D + n]) = pack_bf2(h0, h1);
                    *reinterpret_cast<uint32_t*>(&g_Hlo[(size_t)m * H1D + n]) = pack_bf2(l0, l1);
                } else {
                    #pragma unroll
                    for (int e = 0; e < 2; e++) {
                        int ne = n + e;
                        float ve = e ? v1 : v0;
                        if (ne < 272)       g_MS[m * 16 + ne - 256] = ve;
                        else if (ne < 288)  g_US[m * 16 + ne - 272] = ve;
                        else if (ne == 288) g_ADD[m] = ve;
                    }
                }
            }
        }
    }
}

// ---------------------------------------------------------------------------
// K2: tail mma.sync GEMM + final reduce.
// C[16384,128] = Hcat[16384,768] @ W2tcat[128,768]^T; out = relu(.)·W3 + ...
// Grid 128 CTAs (M=128 each), 8 warps, warp tile 16x128.
// ---------------------------------------------------------------------------
#define TAIL_STAGE 32768                      // 16KB A + 16KB B
#define SMEM_TAIL  (3 * TAIL_STAGE)

static __device__ __forceinline__ void issue_tail(uint32_t sb, int ic, int st,
                                                  int m0, int t)
{
    int seg = ic >> 2;
    int kc  = (ic & 3) * 64;
    const __nv_bfloat16 *Ap, *Bp;
    if (seg == 0)      { Ap = g_Hhi;   Bp = g_W2thi; }
    else if (seg == 1) { Ap = g_Hlo;   Bp = g_W2thi; }
    else               { Ap = g_Hhi;   Bp = g_W2tlo; }
    uint32_t ab = sb + st * TAIL_STAGE;
    uint32_t bb = ab + 16384;
    #pragma unroll
    for (int l = 0; l < 4; l++) {
        int f = t + l * 256;
        int row = f >> 3, kq = (f & 7) * 8;
        cp16(ab + SWZ(row * 128 + kq * 2), Ap + (size_t)(m0 + row) * H1D + kc + kq);
    }
    #pragma unroll
    for (int l = 0; l < 4; l++) {
        int f = t + l * 256;
        int row = f >> 3, kq = (f & 7) * 8;
        cp16(bb + SWZ(row * 128 + kq * 2), Bp + (size_t)row * H1D + kc + kq);
    }
}

__global__ __launch_bounds__(256, 1) void k_mma_tail(
    const float* __restrict__ b2, const float* __restrict__ W3,
    const float* __restrict__ b3, float* __restrict__ out)
{
    extern __shared__ char smem[];
    __shared__ float b2s[128];
    __shared__ float w3s[128];
    uint32_t sb = smem_u32(smem);
    int t = threadIdx.x;
    int lane = t & 31, w = t >> 5;
    int m0 = blockIdx.x * 128;

    if (t < 128) { b2s[t] = b2[t]; w3s[t] = W3[t]; }

    float c[16][4];
    #pragma unroll
    for (int j = 0; j < 16; j++)
        #pragma unroll
        for (int q = 0; q < 4; q++) c[j][q] = 0.f;

    const int NC = 12;
    issue_tail(sb, 0, 0, m0, t); CP_COMMIT();
    issue_tail(sb, 1, 1, m0, t); CP_COMMIT();

    int a_row  = (lane & 15);
    int a_koff = (lane >> 4) * 16;
    int b_row  = ((lane >> 4) & 1) * 8 + (lane & 7);
    int b_koff = ((lane >> 3) & 1) * 16;

    #pragma unroll 1
    for (int ic = 0; ic < NC; ic++) {
        __syncthreads();
        if (ic + 2 < NC) issue_tail(sb, ic + 2, (ic + 2) % 3, m0, t);
        CP_COMMIT();
        CP_WAIT2();
        __syncthreads();

        uint32_t ab = sb + (ic % 3) * TAIL_STAGE;
        uint32_t bb = ab + 16384;
        #pragma unroll
        for (int ks = 0; ks < 4; ks++) {
            uint32_t a[4], b[16][2];
            LDSM4(a[0], a[1], a[2], a[3],
                  ab + SWZ((w * 16 + a_row) * 128 + ks * 32 + a_koff));
            #pragma unroll
            for (int jp = 0; jp < 8; jp++)
                LDSM4(b[2 * jp][0], b[2 * jp][1], b[2 * jp + 1][0], b[2 * jp + 1][1],
                      bb + SWZ((jp * 16 + b_row) * 128 + ks * 32 + b_koff));
            #pragma unroll
            for (int j = 0; j < 16; j++)
                MMA16816(c[j], a, b[j]);
        }
    }

    // Epilogue: relu(c + b2) dot W3, reduce across the 4 lanes sharing a row.
    float p0 = 0.f, p1 = 0.f;
    #pragma unroll
    for (int j = 0; j < 16; j++) {
        int n = j * 8 + (lane & 3) * 2;
        p0 += fmaxf(c[j][0] + b2s[n],     0.f) * w3s[n];
        p0 += fmaxf(c[j][1] + b2s[n + 1], 0.f) * w3s[n + 1];
        p1 += fmaxf(c[j][2] + b2s[n],     0.f) * w3s[n];
        p1 += fmaxf(c[j][3] + b2s[n + 1], 0.f) * w3s[n + 1];
    }
    p0 += __shfl_xor_sync(0xFFFFFFFF, p0, 1);
    p0 += __shfl_xor_sync(0xFFFFFFFF, p0, 2);
    p1 += __shfl_xor_sync(0xFFFFFFFF, p1, 1);
    p1 += __shfl_xor_sync(0xFFFFFFFF, p1, 2);

    if ((lane & 3) == 0) {
        float b3v = b3[0];
        #pragma unroll
        for (int half = 0; half < 2; half++) {
            int m = m0 + w * 16 + (lane >> 2) + half * 8;
            float s = (half ? p1 : p0) + b3v + g_ADD[m];
            #pragma unroll
            for (int i = 0; i < 16; i++) s += g_MS[m * 16 + i] * g_US[m * 16 + i];
            out[m] = s;
        }
    }
}

// ---------------------------------------------------------------------------
extern "C" void kernel_launch(void* const* d_in, const int* in_sizes, int n_in,
                              void* d_out, int out_size)
{
    const float* mv = (const float*)d_in[0];
    const float* uv = (const float*)d_in[1];
    const float* Wm = (const float*)d_in[2];
    const float* bm = (const float*)d_in[3];
    const float* Wu = (const float*)d_in[4];
    const float* bu = (const float*)d_in[5];
    const float* W1 = (const float*)d_in[6];
    const float* b1 = (const float*)d_in[7];
    const float* W2 = (const float*)d_in[8];
    const float* b2 = (const float*)d_in[9];
    const float* W3 = (const float*)d_in[10];
    const float* b3 = (const float*)d_in[11];
    float* out = (float*)d_out;

    cudaFuncSetAttribute(k_mma_main, cudaFuncAttributeMaxDynamicSharedMemorySize, SMEM_MAIN);
    cudaFuncSetAttribute(k_mma_tail, cudaFuncAttributeMaxDynamicSharedMemorySize, SMEM_TAIL);

    // Weight precompute (fresh every call).
    k_combine_gemm<<<dim3(4, 8, 2), 256>>>(Wm, Wu, W1);
    k_small<<<(KD * 16 + NOUT + 255) / 256, 256>>>(Wm, bm, Wu, bu, W1, b1);
    k_convB<<<(NPAD * KD + H2D * H1D + 255) / 256, 256>>>(W2);

    // Main tensor-core GEMM with fused A split. One wave of 128 CTAs.
    k_mma_main<<<BATCH / 128, 512, SMEM_MAIN>>>(mv, uv);

    // Tail tensor-core GEMM + final reduction.
    k_mma_tail<<<BATCH / 128, 256, SMEM_TAIL>>>(b2, W3, b3, out);
}